// round 1
// baseline (speedup 1.0000x reference)
#include <cuda_runtime.h>
#include <cuda_bf16.h>
#include <math.h>

// Problem constants
#define BB 128
#define NN_TOK 1024
#define DD 512
#define SS 64
#define EPS_K 1e-8f
#define M_BIG (BB * NN_TOK)   // 131072

// Scratch (device globals; allocation is forbidden)
__device__ float g_bufA[(size_t)M_BIG * DD];   // 256 MB
__device__ float g_bufB[(size_t)M_BIG * DD];   // 256 MB
__device__ float g_dots[(size_t)BB * SS * NN_TOK]; // 32 MB (dots -> attn2 in place)
__device__ float g_factor[BB * SS];

// ---------------------------------------------------------------------------
// NT GEMM: C[m,n] = alpha * sum_k A[m,k] * B[n,k]  (+bias[n]) (+relu)
// A row-major [M,K], B row-major [N,K]. Batched via grid.z with elem strides.
// ---------------------------------------------------------------------------
template <int BM, int BN, int BK, int TM, int TN, bool RELU, bool HAS_BIAS>
__global__ __launch_bounds__(256) void gemm_nt_kernel(
    const float* __restrict__ A, const float* __restrict__ Bw,
    const float* __restrict__ bias, float* __restrict__ C,
    int M, int N, int K, float alpha,
    long long sA, long long sB, long long sC)
{
    constexpr int THREADS = (BM / TM) * (BN / TN);
    __shared__ float As[BK][BM + 4];
    __shared__ float Bs[BK][BN + 4];

    const int tid = threadIdx.x;
    const int bx = blockIdx.x;  // N tile
    const int by = blockIdx.y;  // M tile
    const int bz = blockIdx.z;  // batch

    A  += bz * sA + (long long)by * BM * K;
    Bw += bz * sB + (long long)bx * BN * K;
    C  += bz * sC;

    const int tx = tid % (BN / TN);
    const int ty = tid / (BN / TN);

    float acc[TM][TN];
#pragma unroll
    for (int i = 0; i < TM; i++)
#pragma unroll
        for (int j = 0; j < TN; j++) acc[i][j] = 0.f;

    for (int k0 = 0; k0 < K; k0 += BK) {
#pragma unroll
        for (int idx = tid * 4; idx < BM * BK; idx += THREADS * 4) {
            int m = idx / BK, kk = idx % BK;
            float4 v = *reinterpret_cast<const float4*>(A + (long long)m * K + k0 + kk);
            As[kk + 0][m] = v.x; As[kk + 1][m] = v.y;
            As[kk + 2][m] = v.z; As[kk + 3][m] = v.w;
        }
#pragma unroll
        for (int idx = tid * 4; idx < BN * BK; idx += THREADS * 4) {
            int n = idx / BK, kk = idx % BK;
            float4 v = *reinterpret_cast<const float4*>(Bw + (long long)n * K + k0 + kk);
            Bs[kk + 0][n] = v.x; Bs[kk + 1][n] = v.y;
            Bs[kk + 2][n] = v.z; Bs[kk + 3][n] = v.w;
        }
        __syncthreads();
#pragma unroll
        for (int kk = 0; kk < BK; kk++) {
            float ra[TM], rb[TN];
#pragma unroll
            for (int i = 0; i < TM; i++) ra[i] = As[kk][ty * TM + i];
#pragma unroll
            for (int j = 0; j < TN; j++) rb[j] = Bs[kk][tx * TN + j];
#pragma unroll
            for (int i = 0; i < TM; i++)
#pragma unroll
                for (int j = 0; j < TN; j++)
                    acc[i][j] = fmaf(ra[i], rb[j], acc[i][j]);
        }
        __syncthreads();
    }

#pragma unroll
    for (int i = 0; i < TM; i++) {
        int m = by * BM + ty * TM + i;
#pragma unroll
        for (int j = 0; j < TN; j += 4) {
            int n = bx * BN + tx * TN + j;
            float4 v;
            float* pv = &v.x;
#pragma unroll
            for (int t = 0; t < 4; t++) {
                float x = acc[i][j + t] * alpha;
                if (HAS_BIAS) x += bias[n + t];
                if (RELU) x = fmaxf(x, 0.f);
                pv[t] = x;
            }
            *reinterpret_cast<float4*>(C + (long long)m * N + n) = v;
        }
    }
}

// ---------------------------------------------------------------------------
// NN GEMM: C[m,n] = sum_k A[m,k] * B[k,n]. A [M,K] row-major, B [K,N] row-major.
// ---------------------------------------------------------------------------
template <int BM, int BN, int BK, int TM, int TN>
__global__ __launch_bounds__(256) void gemm_nn_kernel(
    const float* __restrict__ A, const float* __restrict__ Bw,
    float* __restrict__ C,
    int M, int N, int K,
    long long sA, long long sB, long long sC)
{
    constexpr int THREADS = (BM / TM) * (BN / TN);
    __shared__ float As[BK][BM + 4];
    __shared__ float Bs[BK][BN + 4];

    const int tid = threadIdx.x;
    const int bx = blockIdx.x;  // N tile
    const int by = blockIdx.y;  // M tile
    const int bz = blockIdx.z;

    A  += bz * sA + (long long)by * BM * K;
    Bw += bz * sB + (long long)bx * BN;
    C  += bz * sC;

    const int tx = tid % (BN / TN);
    const int ty = tid / (BN / TN);

    float acc[TM][TN];
#pragma unroll
    for (int i = 0; i < TM; i++)
#pragma unroll
        for (int j = 0; j < TN; j++) acc[i][j] = 0.f;

    for (int k0 = 0; k0 < K; k0 += BK) {
#pragma unroll
        for (int idx = tid * 4; idx < BM * BK; idx += THREADS * 4) {
            int m = idx / BK, kk = idx % BK;
            float4 v = *reinterpret_cast<const float4*>(A + (long long)m * K + k0 + kk);
            As[kk + 0][m] = v.x; As[kk + 1][m] = v.y;
            As[kk + 2][m] = v.z; As[kk + 3][m] = v.w;
        }
#pragma unroll
        for (int idx = tid * 4; idx < BK * BN; idx += THREADS * 4) {
            int kk = idx / BN, n = idx % BN;
            float4 v = *reinterpret_cast<const float4*>(Bw + (long long)(k0 + kk) * N + n);
            *reinterpret_cast<float4*>(&Bs[kk][n]) = v;
        }
        __syncthreads();
#pragma unroll
        for (int kk = 0; kk < BK; kk++) {
            float ra[TM], rb[TN];
#pragma unroll
            for (int i = 0; i < TM; i++) ra[i] = As[kk][ty * TM + i];
#pragma unroll
            for (int j = 0; j < TN; j++) rb[j] = Bs[kk][tx * TN + j];
#pragma unroll
            for (int i = 0; i < TM; i++)
#pragma unroll
                for (int j = 0; j < TN; j++)
                    acc[i][j] = fmaf(ra[i], rb[j], acc[i][j]);
        }
        __syncthreads();
    }

#pragma unroll
    for (int i = 0; i < TM; i++) {
        int m = by * BM + ty * TM + i;
#pragma unroll
        for (int j = 0; j < TN; j += 4) {
            int n = bx * BN + tx * TN + j;
            float4 v = make_float4(acc[i][j], acc[i][j + 1], acc[i][j + 2], acc[i][j + 3]);
            *reinterpret_cast<float4*>(C + (long long)m * N + n) = v;
        }
    }
}

// ---------------------------------------------------------------------------
// factor[b,i] = s_all[b] / s_j[b,i] where s_j = sum_j dots[b,i,j]
// one block per batch, 8 warps; warp w handles rows w, w+8, ...
// ---------------------------------------------------------------------------
__global__ __launch_bounds__(256) void factor_kernel(const float* __restrict__ dots,
                                                     float* __restrict__ factor)
{
    int b = blockIdx.x;
    const float* db = dots + (long long)b * SS * NN_TOK;
    __shared__ float sj[SS];
    __shared__ float stot;
    int w = threadIdx.x >> 5, lane = threadIdx.x & 31;
    for (int i = w; i < SS; i += 8) {
        const float* row = db + (long long)i * NN_TOK;
        float s = 0.f;
        for (int j = lane; j < NN_TOK; j += 32) s += row[j];
#pragma unroll
        for (int o = 16; o; o >>= 1) s += __shfl_xor_sync(0xffffffffu, s, o);
        if (lane == 0) sj[i] = s;
    }
    __syncthreads();
    if (threadIdx.x == 0) {
        float t = 0.f;
        for (int i = 0; i < SS; i++) t += sj[i];
        stot = t;
    }
    __syncthreads();
    if (threadIdx.x < SS)
        factor[b * SS + threadIdx.x] = stot / sj[threadIdx.x];
}

// ---------------------------------------------------------------------------
// per-row: attn = sigmoid(dots * factor); attn_out <- attn;
//          dots <- attn / (rowsum(attn) + eps)   (in place, becomes attn2)
// grid = B*S blocks, 256 threads
// ---------------------------------------------------------------------------
__global__ __launch_bounds__(256) void attn_kernel(float* __restrict__ dots,
                                                   const float* __restrict__ factor,
                                                   float* __restrict__ attn_out)
{
    long long r = blockIdx.x;
    float f = factor[r];
    float* row = dots + r * NN_TOK;
    float* out = attn_out + r * NN_TOK;
    __shared__ float buf[NN_TOK];
    __shared__ float ssum[8];
    __shared__ float stot;
    int tid = threadIdx.x;

    float local = 0.f;
    for (int j = tid; j < NN_TOK; j += 256) {
        float v = 1.f / (1.f + expf(-row[j] * f));
        buf[j] = v;
        local += v;
    }
#pragma unroll
    for (int o = 16; o; o >>= 1) local += __shfl_xor_sync(0xffffffffu, local, o);
    if ((tid & 31) == 0) ssum[tid >> 5] = local;
    __syncthreads();
    if (tid == 0) {
        float t = 0.f;
#pragma unroll
        for (int i = 0; i < 8; i++) t += ssum[i];
        stot = t + EPS_K;
    }
    __syncthreads();
    float inv = 1.f / stot;
    for (int j = tid; j < NN_TOK; j += 256) {
        float v = buf[j];
        out[j] = v;
        row[j] = v * inv;
    }
}

// ---------------------------------------------------------------------------
extern "C" void kernel_launch(void* const* d_in, const int* in_sizes, int n_in,
                              void* d_out, int out_size)
{
    const float* inputs_pe = (const float*)d_in[0];
    const float* inputs    = (const float*)d_in[1];
    const float* slots     = (const float*)d_in[2];
    const float* W1 = (const float*)d_in[3];
    const float* b1 = (const float*)d_in[4];
    const float* W2 = (const float*)d_in[5];
    const float* b2 = (const float*)d_in[6];
    const float* W3 = (const float*)d_in[7];
    const float* b3 = (const float*)d_in[8];

    float* out = (float*)d_out;
    float* updates = out;                                   // [B, S, D]
    float* attn    = out + (long long)BB * SS * DD;         // [B, S, N]

    float *bufA, *bufB, *dotsp, *factp;
    cudaGetSymbolAddress((void**)&bufA,  g_bufA);
    cudaGetSymbolAddress((void**)&bufB,  g_bufB);
    cudaGetSymbolAddress((void**)&dotsp, g_dots);
    cudaGetSymbolAddress((void**)&factp, g_factor);

    const float scale = 0.044194173824159216f;  // 512^-0.5

    // MLP: k = W3 @ relu(W2 @ relu(W1 x + b1) + b2) + b3   (all x@W.T forms)
    dim3 gBig(DD / 128, M_BIG / 128, 1);
    gemm_nt_kernel<128, 128, 16, 8, 8, true,  true><<<gBig, 256>>>(
        inputs_pe, W1, b1, bufA, M_BIG, DD, DD, 1.f, 0, 0, 0);
    gemm_nt_kernel<128, 128, 16, 8, 8, true,  true><<<gBig, 256>>>(
        bufA, W2, b2, bufB, M_BIG, DD, DD, 1.f, 0, 0, 0);
    gemm_nt_kernel<128, 128, 16, 8, 8, false, true><<<gBig, 256>>>(
        bufB, W3, b3, bufA, M_BIG, DD, DD, 1.f, 0, 0, 0);
    // bufA now holds k [B, N, D]

    // dots[b,i,j] = scale * <slots[i], k[b,j]>  : per-batch 64x1024 NT GEMM
    dim3 gDots(NN_TOK / 128, 1, BB);
    gemm_nt_kernel<64, 128, 16, 4, 8, false, false><<<gDots, 256>>>(
        slots, bufA, nullptr, dotsp, SS, NN_TOK, DD, scale,
        0, (long long)NN_TOK * DD, (long long)SS * NN_TOK);

    // row-sum factor, sigmoid + renorm
    factor_kernel<<<BB, 256>>>(dotsp, factp);
    attn_kernel<<<BB * SS, 256>>>(dotsp, factp, attn);
    // dotsp now holds attn2 [B, S, N]

    // updates[b,i,d] = sum_j attn2[b,i,j] * inputs[b,j,d] : per-batch NN GEMM
    dim3 gUpd(DD / 128, 1, BB);
    gemm_nn_kernel<64, 128, 16, 4, 8><<<gUpd, 256>>>(
        dotsp, inputs, updates, SS, DD, NN_TOK,
        (long long)SS * NN_TOK, (long long)NN_TOK * DD, (long long)SS * DD);
}

// round 13
// speedup vs baseline: 1.9554x; 1.9554x over previous
#include <cuda_runtime.h>
#include <cuda_bf16.h>
#include <math.h>
#include <stdint.h>

// Problem constants
#define BB 128
#define NN_TOK 1024
#define DD 512
#define SS 64
#define EPS_K 1e-8f
#define M_BIG (BB * NN_TOK)   // 131072

// ---------------------------------------------------------------------------
// Device scratch (allocation forbidden -> __device__ globals)
// ---------------------------------------------------------------------------
__device__ __align__(16) float g_bufA[(size_t)M_BIG * DD];   // 256 MB
__device__ __align__(16) float g_bufB[(size_t)M_BIG * DD];   // 256 MB
__device__ __align__(16) float g_dots[(size_t)BB * SS * NN_TOK];
__device__ __align__(16) float g_factor[BB * SS];

// ---------------------------------------------------------------------------
// bf16 helpers (generic PTX, sm_80+ -- compiles under compute_103)
// ---------------------------------------------------------------------------
// pack two floats as bf16x2: low half = a (even k), high half = b (odd k)
__device__ __forceinline__ uint32_t pack_bf16x2(float a, float b) {
    uint32_t u;
    asm("cvt.rn.bf16x2.f32 %0, %1, %2;" : "=r"(u) : "f"(b), "f"(a));
    return u;
}

// mma.sync m16n8k16 bf16 -> f32 accum (A row-major, B col-major)
__device__ __forceinline__ void mma_bf16(float* c, const uint32_t* a, const uint32_t* b) {
    asm volatile(
        "mma.sync.aligned.m16n8k16.row.col.f32.bf16.bf16.f32 "
        "{%0,%1,%2,%3}, {%4,%5,%6,%7}, {%8,%9}, {%0,%1,%2,%3};"
        : "+f"(c[0]), "+f"(c[1]), "+f"(c[2]), "+f"(c[3])
        : "r"(a[0]), "r"(a[1]), "r"(a[2]), "r"(a[3]),
          "r"(b[0]), "r"(b[1]));
}

// ---------------------------------------------------------------------------
// MLP layer GEMM on tensor cores (bf16 hi/lo split, mma.sync m16n8k16):
//   C[M_BIG, 512] = A[M_BIG, 512] @ W[512, 512]^T + bias  (opt. ReLU)
// fp32 product approximated as Ah*Bh + Ah*Bl + Al*Bh (lo*lo dropped, ~2^-16).
// CTA tile 128x128, BK=32 (=16 bf16x2 pairs), 8 warps (4x2), warp tile 32x64.
// Single smem stage + register prefetch of next K-chunk.
// Smem: 4 arrays x 128 x 20 u32 = 40 KB static. Stride 20: fragment loads
// (8 rows x 4 consecutive pairs) hit 32 distinct banks.
// ---------------------------------------------------------------------------
#define PSTRIDE 20   // 16 pairs + 4 pad

template <bool RELU>
__global__ __launch_bounds__(256) void mlp_bf16s_kernel(
    const float* __restrict__ A, const float* __restrict__ W,
    const float* __restrict__ bias, float* __restrict__ C)
{
    __shared__ uint32_t AsH[128][PSTRIDE];
    __shared__ uint32_t AsL[128][PSTRIDE];
    __shared__ uint32_t BsH[128][PSTRIDE];
    __shared__ uint32_t BsL[128][PSTRIDE];

    const int tid  = threadIdx.x;
    const int lane = tid & 31;
    const int wid  = tid >> 5;
    const int wm   = wid & 3;          // warp row (0..3) -> 32 M-rows
    const int wn   = wid >> 2;         // warp col (0..1) -> 64 N-cols
    const int g    = lane >> 2;        // groupID (0..7)
    const int tg   = lane & 3;         // thread-in-group (0..3)

    const long long m0 = (long long)blockIdx.y * 128;
    const int       n0 = blockIdx.x * 128;

    const float* Abase = A + m0 * DD;
    const float* Wbase = W + (long long)n0 * DD;

    const int row_l = tid >> 3;        // 0..31 (row within 32-row slab)
    const int c4    = tid & 7;         // float4 index within 32-float chunk

    float4 pa[4], pb[4];

    // preload chunk 0
#pragma unroll
    for (int i = 0; i < 4; i++) {
        int r = i * 32 + row_l;
        pa[i] = *reinterpret_cast<const float4*>(Abase + (long long)r * DD + c4 * 4);
        pb[i] = *reinterpret_cast<const float4*>(Wbase + (long long)r * DD + c4 * 4);
    }

    float acc[2][8][4];
#pragma unroll
    for (int mf = 0; mf < 2; mf++)
#pragma unroll
        for (int nf = 0; nf < 8; nf++)
#pragma unroll
            for (int t = 0; t < 4; t++) acc[mf][nf][t] = 0.f;

    for (int kc = 0; kc < DD / 32; kc++) {
        __syncthreads();   // previous chunk's compute done; smem reusable
#pragma unroll
        for (int i = 0; i < 4; i++) {
            int r = i * 32 + row_l;
            // A: split into hi/lo bf16
            float ax = pa[i].x, ay = pa[i].y, az = pa[i].z, aw = pa[i].w;
            float hx = __bfloat162float(__float2bfloat16_rn(ax));
            float hy = __bfloat162float(__float2bfloat16_rn(ay));
            float hz = __bfloat162float(__float2bfloat16_rn(az));
            float hw = __bfloat162float(__float2bfloat16_rn(aw));
            AsH[r][c4 * 2]     = pack_bf16x2(hx, hy);
            AsH[r][c4 * 2 + 1] = pack_bf16x2(hz, hw);
            AsL[r][c4 * 2]     = pack_bf16x2(ax - hx, ay - hy);
            AsL[r][c4 * 2 + 1] = pack_bf16x2(az - hz, aw - hw);
            // B (= W rows): split into hi/lo bf16
            float bx = pb[i].x, by = pb[i].y, bz = pb[i].z, bw = pb[i].w;
            float gx = __bfloat162float(__float2bfloat16_rn(bx));
            float gy = __bfloat162float(__float2bfloat16_rn(by));
            float gz = __bfloat162float(__float2bfloat16_rn(bz));
            float gw = __bfloat162float(__float2bfloat16_rn(bw));
            BsH[r][c4 * 2]     = pack_bf16x2(gx, gy);
            BsH[r][c4 * 2 + 1] = pack_bf16x2(gz, gw);
            BsL[r][c4 * 2]     = pack_bf16x2(bx - gx, by - gy);
            BsL[r][c4 * 2 + 1] = pack_bf16x2(bz - gz, bw - gw);
        }
        __syncthreads();

        // prefetch next chunk while computing this one
        if (kc + 1 < DD / 32) {
            int k0g = (kc + 1) * 32;
#pragma unroll
            for (int i = 0; i < 4; i++) {
                int r = i * 32 + row_l;
                pa[i] = *reinterpret_cast<const float4*>(Abase + (long long)r * DD + k0g + c4 * 4);
                pb[i] = *reinterpret_cast<const float4*>(Wbase + (long long)r * DD + k0g + c4 * 4);
            }
        }

        // two k16 steps per 32-chunk; pair index p = ks*8 + tg (+4)
#pragma unroll
        for (int ks = 0; ks < 2; ks++) {
            const int k0 = ks * 8;
            uint32_t ah[2][4], al[2][4], bh[8][2], bl[8][2];
#pragma unroll
            for (int mf = 0; mf < 2; mf++) {
                int rm = wm * 32 + mf * 16 + g;
                ah[mf][0] = AsH[rm][k0 + tg];
                ah[mf][1] = AsH[rm + 8][k0 + tg];
                ah[mf][2] = AsH[rm][k0 + tg + 4];
                ah[mf][3] = AsH[rm + 8][k0 + tg + 4];
                al[mf][0] = AsL[rm][k0 + tg];
                al[mf][1] = AsL[rm + 8][k0 + tg];
                al[mf][2] = AsL[rm][k0 + tg + 4];
                al[mf][3] = AsL[rm + 8][k0 + tg + 4];
            }
#pragma unroll
            for (int nf = 0; nf < 8; nf++) {
                int rn = wn * 64 + nf * 8 + g;
                bh[nf][0] = BsH[rn][k0 + tg];
                bh[nf][1] = BsH[rn][k0 + tg + 4];
                bl[nf][0] = BsL[rn][k0 + tg];
                bl[nf][1] = BsL[rn][k0 + tg + 4];
            }
#pragma unroll
            for (int mf = 0; mf < 2; mf++)
#pragma unroll
                for (int nf = 0; nf < 8; nf++) {
                    mma_bf16(acc[mf][nf], ah[mf], bh[nf]);
                    mma_bf16(acc[mf][nf], ah[mf], bl[nf]);
                    mma_bf16(acc[mf][nf], al[mf], bh[nf]);
                }
        }
    }

    // epilogue: bias (+ReLU), fp32 out
#pragma unroll
    for (int mf = 0; mf < 2; mf++) {
        long long r0 = m0 + wm * 32 + mf * 16 + g;
#pragma unroll
        for (int nf = 0; nf < 8; nf++) {
            int c = n0 + wn * 64 + nf * 8 + 2 * tg;
            float b0 = bias[c], b1 = bias[c + 1];
            float v0 = acc[mf][nf][0] + b0;
            float v1 = acc[mf][nf][1] + b1;
            float v2 = acc[mf][nf][2] + b0;
            float v3 = acc[mf][nf][3] + b1;
            if (RELU) {
                v0 = fmaxf(v0, 0.f); v1 = fmaxf(v1, 0.f);
                v2 = fmaxf(v2, 0.f); v3 = fmaxf(v3, 0.f);
            }
            *reinterpret_cast<float2*>(C + r0 * DD + c)       = make_float2(v0, v1);
            *reinterpret_cast<float2*>(C + (r0 + 8) * DD + c) = make_float2(v2, v3);
        }
    }
}

// ---------------------------------------------------------------------------
// SIMT NT GEMM for dots (proven in R1)
// ---------------------------------------------------------------------------
template <int BM, int BN, int BK, int TM, int TN>
__global__ __launch_bounds__(256) void gemm_nt_kernel(
    const float* __restrict__ A, const float* __restrict__ Bw,
    float* __restrict__ C, int M, int N, int K, float alpha,
    long long sA, long long sB, long long sC)
{
    constexpr int THREADS = (BM / TM) * (BN / TN);
    __shared__ float As[BK][BM + 4];
    __shared__ float Bs[BK][BN + 4];
    const int tid = threadIdx.x;
    const int bx = blockIdx.x, by = blockIdx.y, bz = blockIdx.z;
    A  += bz * sA + (long long)by * BM * K;
    Bw += bz * sB + (long long)bx * BN * K;
    C  += bz * sC;
    const int tx = tid % (BN / TN);
    const int ty = tid / (BN / TN);
    float acc[TM][TN];
#pragma unroll
    for (int i = 0; i < TM; i++)
#pragma unroll
        for (int j = 0; j < TN; j++) acc[i][j] = 0.f;
    for (int k0 = 0; k0 < K; k0 += BK) {
#pragma unroll
        for (int idx = tid * 4; idx < BM * BK; idx += THREADS * 4) {
            int m = idx / BK, kk = idx % BK;
            float4 v = *reinterpret_cast<const float4*>(A + (long long)m * K + k0 + kk);
            As[kk + 0][m] = v.x; As[kk + 1][m] = v.y;
            As[kk + 2][m] = v.z; As[kk + 3][m] = v.w;
        }
#pragma unroll
        for (int idx = tid * 4; idx < BN * BK; idx += THREADS * 4) {
            int n = idx / BK, kk = idx % BK;
            float4 v = *reinterpret_cast<const float4*>(Bw + (long long)n * K + k0 + kk);
            Bs[kk + 0][n] = v.x; Bs[kk + 1][n] = v.y;
            Bs[kk + 2][n] = v.z; Bs[kk + 3][n] = v.w;
        }
        __syncthreads();
#pragma unroll
        for (int kk = 0; kk < BK; kk++) {
            float ra[TM], rb[TN];
#pragma unroll
            for (int i = 0; i < TM; i++) ra[i] = As[kk][ty * TM + i];
#pragma unroll
            for (int j = 0; j < TN; j++) rb[j] = Bs[kk][tx * TN + j];
#pragma unroll
            for (int i = 0; i < TM; i++)
#pragma unroll
                for (int j = 0; j < TN; j++)
                    acc[i][j] = fmaf(ra[i], rb[j], acc[i][j]);
        }
        __syncthreads();
    }
#pragma unroll
    for (int i = 0; i < TM; i++) {
        int m = by * BM + ty * TM + i;
#pragma unroll
        for (int j = 0; j < TN; j += 4) {
            int n = bx * BN + tx * TN + j;
            float4 v = make_float4(acc[i][j] * alpha, acc[i][j + 1] * alpha,
                                   acc[i][j + 2] * alpha, acc[i][j + 3] * alpha);
            *reinterpret_cast<float4*>(C + (long long)m * N + n) = v;
        }
    }
}

// SIMT NN GEMM for updates (proven in R1)
template <int BM, int BN, int BK, int TM, int TN>
__global__ __launch_bounds__(256) void gemm_nn_kernel(
    const float* __restrict__ A, const float* __restrict__ Bw,
    float* __restrict__ C, int M, int N, int K,
    long long sA, long long sB, long long sC)
{
    constexpr int THREADS = (BM / TM) * (BN / TN);
    __shared__ float As[BK][BM + 4];
    __shared__ float Bs[BK][BN + 4];
    const int tid = threadIdx.x;
    const int bx = blockIdx.x, by = blockIdx.y, bz = blockIdx.z;
    A  += bz * sA + (long long)by * BM * K;
    Bw += bz * sB + (long long)bx * BN;
    C  += bz * sC;
    const int tx = tid % (BN / TN);
    const int ty = tid / (BN / TN);
    float acc[TM][TN];
#pragma unroll
    for (int i = 0; i < TM; i++)
#pragma unroll
        for (int j = 0; j < TN; j++) acc[i][j] = 0.f;
    for (int k0 = 0; k0 < K; k0 += BK) {
#pragma unroll
        for (int idx = tid * 4; idx < BM * BK; idx += THREADS * 4) {
            int m = idx / BK, kk = idx % BK;
            float4 v = *reinterpret_cast<const float4*>(A + (long long)m * K + k0 + kk);
            As[kk + 0][m] = v.x; As[kk + 1][m] = v.y;
            As[kk + 2][m] = v.z; As[kk + 3][m] = v.w;
        }
#pragma unroll
        for (int idx = tid * 4; idx < BK * BN; idx += THREADS * 4) {
            int kk = idx / BN, n = idx % BN;
            float4 v = *reinterpret_cast<const float4*>(Bw + (long long)(k0 + kk) * N + n);
            *reinterpret_cast<float4*>(&Bs[kk][n]) = v;
        }
        __syncthreads();
#pragma unroll
        for (int kk = 0; kk < BK; kk++) {
            float ra[TM], rb[TN];
#pragma unroll
            for (int i = 0; i < TM; i++) ra[i] = As[kk][ty * TM + i];
#pragma unroll
            for (int j = 0; j < TN; j++) rb[j] = Bs[kk][tx * TN + j];
#pragma unroll
            for (int i = 0; i < TM; i++)
#pragma unroll
                for (int j = 0; j < TN; j++)
                    acc[i][j] = fmaf(ra[i], rb[j], acc[i][j]);
        }
        __syncthreads();
    }
#pragma unroll
    for (int i = 0; i < TM; i++) {
        int m = by * BM + ty * TM + i;
#pragma unroll
        for (int j = 0; j < TN; j += 4) {
            int n = bx * BN + tx * TN + j;
            float4 v = make_float4(acc[i][j], acc[i][j + 1], acc[i][j + 2], acc[i][j + 3]);
            *reinterpret_cast<float4*>(C + (long long)m * N + n) = v;
        }
    }
}

// factor[b,i] = s_all[b] / s_j[b,i]
__global__ __launch_bounds__(256) void factor_kernel(const float* __restrict__ dots,
                                                     float* __restrict__ factor)
{
    int b = blockIdx.x;
    const float* db = dots + (long long)b * SS * NN_TOK;
    __shared__ float sj[SS];
    __shared__ float stot;
    int w = threadIdx.x >> 5, lane = threadIdx.x & 31;
    for (int i = w; i < SS; i += 8) {
        const float* row = db + (long long)i * NN_TOK;
        float s = 0.f;
        for (int j = lane; j < NN_TOK; j += 32) s += row[j];
#pragma unroll
        for (int o = 16; o; o >>= 1) s += __shfl_xor_sync(0xffffffffu, s, o);
        if (lane == 0) sj[i] = s;
    }
    __syncthreads();
    if (threadIdx.x == 0) {
        float t = 0.f;
        for (int i = 0; i < SS; i++) t += sj[i];
        stot = t;
    }
    __syncthreads();
    if (threadIdx.x < SS)
        factor[b * SS + threadIdx.x] = stot / sj[threadIdx.x];
}

// attn = sigmoid(dots*factor); out attn; dots <- attn/(rowsum(attn)+eps)
__global__ __launch_bounds__(256) void attn_kernel(float* __restrict__ dots,
                                                   const float* __restrict__ factor,
                                                   float* __restrict__ attn_out)
{
    long long r = blockIdx.x;
    float f = factor[r];
    float* row = dots + r * NN_TOK;
    float* out = attn_out + r * NN_TOK;
    __shared__ float buf[NN_TOK];
    __shared__ float ssum[8];
    __shared__ float stot;
    int tid = threadIdx.x;
    float local = 0.f;
    for (int j = tid; j < NN_TOK; j += 256) {
        float v = 1.f / (1.f + expf(-row[j] * f));
        buf[j] = v;
        local += v;
    }
#pragma unroll
    for (int o = 16; o; o >>= 1) local += __shfl_xor_sync(0xffffffffu, local, o);
    if ((tid & 31) == 0) ssum[tid >> 5] = local;
    __syncthreads();
    if (tid == 0) {
        float t = 0.f;
#pragma unroll
        for (int i = 0; i < 8; i++) t += ssum[i];
        stot = t + EPS_K;
    }
    __syncthreads();
    float inv = 1.f / stot;
    for (int j = tid; j < NN_TOK; j += 256) {
        float v = buf[j];
        out[j] = v;
        row[j] = v * inv;
    }
}

// ---------------------------------------------------------------------------
extern "C" void kernel_launch(void* const* d_in, const int* in_sizes, int n_in,
                              void* d_out, int out_size)
{
    const float* inputs_pe = (const float*)d_in[0];
    const float* inputs    = (const float*)d_in[1];
    const float* slots     = (const float*)d_in[2];
    const float* W1 = (const float*)d_in[3];
    const float* b1 = (const float*)d_in[4];
    const float* W2 = (const float*)d_in[5];
    const float* b2 = (const float*)d_in[6];
    const float* W3 = (const float*)d_in[7];
    const float* b3 = (const float*)d_in[8];

    float* out = (float*)d_out;
    float* updates = out;                           // [B, S, D]
    float* attn    = out + (long long)BB * SS * DD; // [B, S, N]

    float *bufA, *bufB, *dotsp, *factp;
    cudaGetSymbolAddress((void**)&bufA,  g_bufA);
    cudaGetSymbolAddress((void**)&bufB,  g_bufB);
    cudaGetSymbolAddress((void**)&dotsp, g_dots);
    cudaGetSymbolAddress((void**)&factp, g_factor);

    const float scale = 0.044194173824159216f;  // 512^-0.5

    // MLP on tensor cores (bf16 hi/lo split mma.sync):
    //   k = W3 @ relu(W2 @ relu(W1 x + b1) + b2) + b3
    dim3 gMLP(DD / 128, M_BIG / 128, 1);
    mlp_bf16s_kernel<true ><<<gMLP, 256>>>(inputs_pe, W1, b1, bufA);
    mlp_bf16s_kernel<true ><<<gMLP, 256>>>(bufA,      W2, b2, bufB);
    mlp_bf16s_kernel<false><<<gMLP, 256>>>(bufB,      W3, b3, bufA);
    // bufA now holds k [B, N, D] fp32

    // dots[b,i,j] = scale * <slots[i], k[b,j]>
    dim3 gDots(NN_TOK / 128, 1, BB);
    gemm_nt_kernel<64, 128, 16, 4, 8><<<gDots, 256>>>(
        slots, bufA, dotsp, SS, NN_TOK, DD, scale,
        0, (long long)NN_TOK * DD, (long long)SS * NN_TOK);

    factor_kernel<<<BB, 256>>>(dotsp, factp);
    attn_kernel<<<BB * SS, 256>>>(dotsp, factp, attn);
    // dotsp now holds attn2 [B, S, N]

    // updates[b,i,d] = sum_j attn2[b,i,j] * inputs[b,j,d]
    dim3 gUpd(DD / 128, 1, BB);
    gemm_nn_kernel<64, 128, 16, 4, 8><<<gUpd, 256>>>(
        dotsp, inputs, updates, SS, DD, NN_TOK,
        (long long)SS * NN_TOK, (long long)NN_TOK * DD, (long long)SS * DD);
}